// round 16
// baseline (speedup 1.0000x reference)
#include <cuda_runtime.h>
#include <cuda_fp16.h>
#include <cstdint>

// ---------------------------------------------------------------------------
// CodebookLayer: out[m] = codebook[argmax_c (2*x.c - ||c||^2)]
//
// Round 16: INT8 IMMA screen GEMM (R15 mainloop, structural limit) with
// FUSED candidate extraction in the epilogue: per-CTA local-max filter
// (margin-sound: global candidates always pass) appends (score,col) pairs
// to per-row lists; no 128MB score tensor. c2 fused into cb convert.
// Exact fp64 rescore of survivors unchanged.
// ---------------------------------------------------------------------------

#define MDIM 8192
#define CDIM 8192
#define KDIM 1024
#define QSCALE 25.0f
#define DEQ (2.0f / (QSCALE * QSCALE))   // 2/625
#define MARGIN 10.0f
#define CAP 256                           // per-row candidate list capacity

__device__ int8_t  g_x8 [(size_t)MDIM * KDIM];
__device__ int8_t  g_cb8[(size_t)CDIM * KDIM];
__device__ float   g_c2[CDIM];
__device__ int     g_cnt[MDIM];
__device__ float2  g_cand[(size_t)MDIM * CAP];    // (score, col-as-float-bits)

// ---------------- helpers ---------------------------------------------------
__device__ __forceinline__ uint32_t smem_u32(const void* p) {
    uint32_t a;
    asm("{ .reg .u64 t; cvta.to.shared.u64 t, %1; cvt.u32.u64 %0, t; }"
        : "=r"(a) : "l"(p));
    return a;
}
__device__ __forceinline__ void cp16(uint32_t s, const void* g) {
    asm volatile("cp.async.cg.shared.global [%0], [%1], 16;"
                 :: "r"(s), "l"(g) : "memory");
}
__device__ __forceinline__ void ldsm4(uint32_t* r, uint32_t addr) {
    asm volatile("ldmatrix.sync.aligned.m8n8.x4.shared.b16 {%0,%1,%2,%3}, [%4];"
        : "=r"(r[0]), "=r"(r[1]), "=r"(r[2]), "=r"(r[3]) : "r"(addr));
}
__device__ __forceinline__ void mma_s8(int* d, const uint32_t* a,
                                       uint32_t b0, uint32_t b1) {
    asm volatile(
        "mma.sync.aligned.m16n8k32.row.col.s32.s8.s8.s32 "
        "{%0,%1,%2,%3}, {%4,%5,%6,%7}, {%8,%9}, {%0,%1,%2,%3};"
        : "+r"(d[0]), "+r"(d[1]), "+r"(d[2]), "+r"(d[3])
        : "r"(a[0]), "r"(a[1]), "r"(a[2]), "r"(a[3]), "r"(b0), "r"(b1));
}
__device__ __forceinline__ void mbar_init(uint32_t addr, uint32_t cnt) {
    asm volatile("mbarrier.init.shared.b64 [%0], %1;" :: "r"(addr), "r"(cnt) : "memory");
}
__device__ __forceinline__ void mbar_wait(uint32_t addr, uint32_t parity) {
    asm volatile(
        "{\n\t.reg .pred P;\n"
        "WL_%=:\n\t"
        "mbarrier.try_wait.parity.acquire.cta.shared::cta.b64 P, [%0], %1, 0x989680;\n\t"
        "@P bra WD_%=;\n\t"
        "bra WL_%=;\n"
        "WD_%=:\n\t}"
        :: "r"(addr), "r"(parity) : "memory");
}
__device__ __forceinline__ void mbar_arrive(uint32_t addr) {
    asm volatile("mbarrier.arrive.release.cta.shared::cta.b64 _, [%0];"
                 :: "r"(addr) : "memory");
}
__device__ __forceinline__ void cpasync_mbar_arrive_noinc(uint32_t addr) {
    asm volatile("cp.async.mbarrier.arrive.noinc.shared.b64 [%0];"
                 :: "r"(addr) : "memory");
}

// ---------------- kernel 0a: fp32 -> s8 (x) ---------------------------------
__device__ __forceinline__ uint32_t q4(float4 v) {
    int a = __float2int_rn(v.x * QSCALE);
    int b = __float2int_rn(v.y * QSCALE);
    int c = __float2int_rn(v.z * QSCALE);
    int d = __float2int_rn(v.w * QSCALE);
    a = max(-127, min(127, a)); b = max(-127, min(127, b));
    c = max(-127, min(127, c)); d = max(-127, min(127, d));
    return (uint32_t)(uint8_t)a | ((uint32_t)(uint8_t)b << 8) |
           ((uint32_t)(uint8_t)c << 16) | ((uint32_t)(uint8_t)d << 24);
}
__global__ void convert_s8(const float* __restrict__ s,
                           int8_t* __restrict__ d, int n) {
    int i = (blockIdx.x * blockDim.x + threadIdx.x) * 8;
    if (i >= n) return;
    float4 v0 = *reinterpret_cast<const float4*>(s + i);
    float4 v1 = *reinterpret_cast<const float4*>(s + i + 4);
    uint2 o; o.x = q4(v0); o.y = q4(v1);
    *reinterpret_cast<uint2*>(d + i) = o;
}

// ---------------- kernel 0b: cb convert + row norms (fused) ------------------
__global__ __launch_bounds__(256) void convert_cb_c2(
    const float* __restrict__ cb, int8_t* __restrict__ d)
{
    __shared__ float sred[8];
    const int row  = blockIdx.x;
    const int t    = threadIdx.x;
    const int lane = t & 31;
    const int wrp  = t >> 5;
    float4 v = *reinterpret_cast<const float4*>(cb + (size_t)row * KDIM + t * 4);
    *reinterpret_cast<uint32_t*>(d + (size_t)row * KDIM + t * 4) = q4(v);
    float s = v.x * v.x + v.y * v.y + v.z * v.z + v.w * v.w;
    #pragma unroll
    for (int o = 16; o; o >>= 1) s += __shfl_xor_sync(0xffffffffu, s, o);
    if (lane == 0) sred[wrp] = s;
    __syncthreads();
    if (t == 0) {
        float tot = 0.f;
        #pragma unroll
        for (int w = 0; w < 8; w++) tot += sred[w];
        g_c2[row] = tot;
    }
    if (t == 0 && row < MDIM / 8) {
        // zero 8 counters per block across first 1024 blocks: cheap fuse
    }
}

// ---------------- kernel 0c: zero per-row counters ---------------------------
__global__ void init_cnt() {
    int i = blockIdx.x * blockDim.x + threadIdx.x;
    if (i < MDIM) g_cnt[i] = 0;
}

// ---------------- kernel 2: int8 screen GEMM + fused candidate extract ------
// BM=BN=128, BK=128 (128B rows, SW128). 320 thr: warps 0-7 consumers
// (64x32, s32 acc), warps 8 (A) / 9 (B) producers. 3-stage mbar pipeline.
#define NSTAGE 3
#define TILE_BYTES  16384
#define STAGE_BYTES 32768
#define NS (KDIM / 128)            // 8 k-stages
#define SMEM_TOT (1024 + NSTAGE * STAGE_BYTES)

__global__ __launch_bounds__(320, 2) void screen_gemm() {
    extern __shared__ __align__(1024) char smem[];
    const uint32_t base  = smem_u32(smem);
    const uint32_t mb    = base;                 // full[s]=+s*16, empty[s]=+s*16+8
    const uint32_t tiles = base + 1024;
    float* s_sc = reinterpret_cast<float*>(smem + 1024);  // 128x128 f32 (64KB)

    const int t    = threadIdx.x;
    const int lane = t & 31;
    const int wid  = t >> 5;
    const int bm   = blockIdx.y * 128;
    const int bn   = blockIdx.x * 128;

    if (t == 0) {
        #pragma unroll
        for (int s = 0; s < NSTAGE; s++) {
            mbar_init(mb + s * 16,     64);
            mbar_init(mb + s * 16 + 8, 8);
        }
    }
    __syncthreads();

    if (wid >= 8) {
        // ================= PRODUCER (warp 8: A, warp 9: B) ==================
        const int pw   = wid - 8;
        const int ch   = lane & 7;
        const int row0 = lane >> 3;
        const int8_t* gsrc = (pw == 0)
            ? g_x8  + (size_t)(bm + row0) * KDIM + ch * 16
            : g_cb8 + (size_t)(bn + row0) * KDIM + ch * 16;
        const uint32_t tile_off = (uint32_t)pw * TILE_BYTES;
        const uint32_t rbase = (uint32_t)row0 * 128;
        const uint32_t sw0 = (uint32_t)((ch ^ row0) << 4);
        const uint32_t sw1 = (uint32_t)((ch ^ row0 ^ 4) << 4);

        int b = 0, ep = 0;
        for (int s = 0; s < NS; s++) {
            if (s >= NSTAGE) mbar_wait(mb + b * 16 + 8, ep);
            const uint32_t so = tiles + b * STAGE_BYTES + tile_off + rbase;
            const int8_t* g = gsrc + s * 128;
            #pragma unroll
            for (int i = 0; i < 32; i++)
                cp16(so + (uint32_t)i * 512 + ((i & 1) ? sw1 : sw0),
                     g + (size_t)i * 4 * KDIM);
            cpasync_mbar_arrive_noinc(mb + b * 16);
            if (++b == NSTAGE) { b = 0; if (s >= NSTAGE) ep ^= 1; }
        }
        return;
    }

    // ===================== CONSUMER (warps 0-7, 64x32 tiles) ================
    const int wm = wid >> 2;
    const int wn = wid & 3;
    const int rbase = lane & 15;
    const uint32_t lh = (uint32_t)(lane >> 4);

    uint32_t off[6];
    #pragma unroll
    for (int mi = 0; mi < 4; mi++) {
        int row = wm * 64 + mi * 16 + rbase;
        off[mi] = (uint32_t)row * 128 + ((lh ^ (uint32_t)(row & 7)) << 4);
    }
    #pragma unroll
    for (int g = 0; g < 2; g++) {
        int row = wn * 32 + g * 16 + rbase;
        off[4 + g] = TILE_BYTES + (uint32_t)row * 128 +
                     ((lh ^ (uint32_t)(row & 7)) << 4);
    }

    int acc[4][4][4];
    #pragma unroll
    for (int i = 0; i < 4; i++)
        #pragma unroll
        for (int j = 0; j < 4; j++)
            #pragma unroll
            for (int k = 0; k < 4; k++) acc[i][j][k] = 0;

    uint32_t fa[4][4], fb[2][4];

    #define LOADK(As, x)                                                      \
        {                                                                     \
            ldsm4(fa[0], (As) + (off[0] ^ (x))); ldsm4(fa[1], (As) + (off[1] ^ (x))); \
            ldsm4(fa[2], (As) + (off[2] ^ (x))); ldsm4(fa[3], (As) + (off[3] ^ (x))); \
            ldsm4(fb[0], (As) + (off[4] ^ (x))); ldsm4(fb[1], (As) + (off[5] ^ (x))); \
        }
    #define MMAK()                                                            \
        {                                                                     \
            _Pragma("unroll")                                                 \
            for (int mi = 0; mi < 4; mi++)                                    \
                _Pragma("unroll")                                             \
                for (int ni = 0; ni < 4; ni++)                                \
                    mma_s8(acc[mi][ni], fa[mi],                               \
                           fb[ni >> 1][ni & 1], fb[ni >> 1][(ni & 1) + 2]);   \
        }

    int b = 0, pf = 0;
    for (int s = 0; s < NS; s++) {
        mbar_wait(mb + b * 16, pf);
        const uint32_t As = tiles + b * STAGE_BYTES;

        LOADK(As, 0x00u)  MMAK()
        LOADK(As, 0x20u)  MMAK()
        LOADK(As, 0x40u)  MMAK()
        LOADK(As, 0x60u)
        if (lane == 0) mbar_arrive(mb + b * 16 + 8);
        MMAK()

        if (++b == NSTAGE) { b = 0; pf ^= 1; }
    }

    // ---- epilogue phase 1: dequantized scores -> smem (consumers only) ----
    asm volatile("bar.sync 1, 256;" ::: "memory");   // all ldsm done: safe to reuse tiles

    #pragma unroll
    for (int ni = 0; ni < 4; ni++) {
        int nl = wn * 32 + ni * 8 + 2 * (lane & 3);
        float c2a = g_c2[bn + nl];
        float c2b = g_c2[bn + nl + 1];
        #pragma unroll
        for (int mi = 0; mi < 4; mi++) {
            int rl = wm * 64 + mi * 16 + (lane >> 2);
            float2 v0 = make_float2(DEQ * (float)acc[mi][ni][0] - c2a,
                                    DEQ * (float)acc[mi][ni][1] - c2b);
            float2 v1 = make_float2(DEQ * (float)acc[mi][ni][2] - c2a,
                                    DEQ * (float)acc[mi][ni][3] - c2b);
            *reinterpret_cast<float2*>(&s_sc[rl * 128 + nl])       = v0;
            *reinterpret_cast<float2*>(&s_sc[(rl + 8) * 128 + nl]) = v1;
        }
    }
    asm volatile("bar.sync 1, 256;" ::: "memory");

    // ---- epilogue phase 2: per-row local max + margin append ----
    const int r0 = wid * 16;
    for (int r = r0; r < r0 + 16; r++) {
        float v[4];
        float vmax = -3.4e38f;
        #pragma unroll
        for (int j = 0; j < 4; j++) {
            v[j] = s_sc[r * 128 + lane + 32 * j];
            vmax = fmaxf(vmax, v[j]);
        }
        #pragma unroll
        for (int o = 16; o; o >>= 1)
            vmax = fmaxf(vmax, __shfl_xor_sync(0xffffffffu, vmax, o));
        const float th = vmax - MARGIN;
        const int gm = bm + r;
        #pragma unroll
        for (int j = 0; j < 4; j++) {
            if (v[j] >= th) {
                int idx = atomicAdd(&g_cnt[gm], 1);
                if (idx < CAP)
                    g_cand[(size_t)gm * CAP + idx] =
                        make_float2(v[j], __int_as_float(bn + lane + 32 * j));
            }
        }
    }
}

// ---------------- kernel 3: select + exact fp64 rescore ----------------------
#define MAXSURV 64

__global__ __launch_bounds__(256) void select_rescore(
    const float* __restrict__ x, const float* __restrict__ cb,
    float* __restrict__ out)
{
    __shared__ float  xs[KDIM];
    __shared__ float  smax[8];
    __shared__ double sred[2][8];
    __shared__ float2 sc[CAP];
    __shared__ int    surv[MAXSURV];
    __shared__ int    nsurv;

    const int m    = blockIdx.x;
    const int t    = threadIdx.x;
    const int lane = t & 31;
    const int wrp  = t >> 5;

    {
        const float4* src = reinterpret_cast<const float4*>(x + (size_t)m * KDIM);
        reinterpret_cast<float4*>(xs)[t] = src[t];
    }
    if (t == 0) nsurv = 0;

    const int nc = min(g_cnt[m], CAP);

    float lmax = -3.4e38f;
    if (t < nc) {
        float2 p = g_cand[(size_t)m * CAP + t];
        sc[t] = p;
        lmax = p.x;
    }
    #pragma unroll
    for (int o = 16; o; o >>= 1)
        lmax = fmaxf(lmax, __shfl_xor_sync(0xffffffffu, lmax, o));
    if (lane == 0) smax[wrp] = lmax;
    __syncthreads();
    float rowmax = smax[0];
    #pragma unroll
    for (int w = 1; w < 8; w++) rowmax = fmaxf(rowmax, smax[w]);
    const float th = rowmax - MARGIN;

    if (t < nc && sc[t].x >= th) {
        int p = atomicAdd(&nsurv, 1);
        if (p < MAXSURV) surv[p] = __float_as_int(sc[t].y);
    }
    __syncthreads();
    const int ns = min(nsurv, MAXSURV);

    double bestS = -1e300;
    int    bestI = 0x7FFFFFFF;
    for (int ci = 0; ci < ns; ci++) {
        int c = surv[ci];
        const float* crow = cb + (size_t)c * KDIM;
        double s = 0.0, cc = 0.0;
        for (int d = t; d < KDIM; d += 256) {
            double cv = (double)crow[d];
            s  += (double)xs[d] * cv;
            cc += cv * cv;
        }
        #pragma unroll
        for (int o = 16; o; o >>= 1) {
            s  += __shfl_xor_sync(0xffffffffu, s,  o);
            cc += __shfl_xor_sync(0xffffffffu, cc, o);
        }
        if (lane == 0) { sred[0][wrp] = s; sred[1][wrp] = cc; }
        __syncthreads();
        double st = 0.0, ct = 0.0;
        #pragma unroll
        for (int w = 0; w < 8; w++) { st += sred[0][w]; ct += sred[1][w]; }
        __syncthreads();
        double scv = 2.0 * st - ct;
        if (scv > bestS || (scv == bestS && c < bestI)) { bestS = scv; bestI = c; }
    }

    const float4* src = reinterpret_cast<const float4*>(cb + (size_t)bestI * KDIM);
    float4* dst = reinterpret_cast<float4*>(out + (size_t)m * KDIM);
    dst[t] = src[t];
}

// ---------------- launch ------------------------------------------------------
extern "C" void kernel_launch(void* const* d_in, const int* in_sizes, int n_in,
                              void* d_out, int out_size)
{
    const float* x  = (const float*)d_in[0];   // [8192, 1024]
    const float* cb = (const float*)d_in[1];   // [8192, 1024]
    float* out = (float*)d_out;

    const int NX = MDIM * KDIM;

    int8_t *x8_p = nullptr, *cb8_p = nullptr;
    cudaGetSymbolAddress((void**)&x8_p, g_x8);
    cudaGetSymbolAddress((void**)&cb8_p, g_cb8);

    cudaFuncSetAttribute(screen_gemm,
                         cudaFuncAttributeMaxDynamicSharedMemorySize, SMEM_TOT);

    init_cnt<<<MDIM / 256, 256>>>();
    convert_s8<<<NX / 2048, 256>>>(x, x8_p, NX);
    convert_cb_c2<<<CDIM, 256>>>(cb, cb8_p);

    dim3 grid(CDIM / 128, MDIM / 128);
    screen_gemm<<<grid, 320, SMEM_TOT>>>();

    select_rescore<<<MDIM, 256>>>(x, cb, out);
}

// round 17
// speedup vs baseline: 1.1167x; 1.1167x over previous
#include <cuda_runtime.h>
#include <cuda_fp16.h>
#include <cstdint>

// ---------------------------------------------------------------------------
// CodebookLayer: out[m] = codebook[argmax_c (2*x.c - ||c||^2)]
//
// Round 17: INT8 IMMA screen GEMM (R15 mainloop) + REGISTER-PATH fused
// candidate extraction (shfl row-max + shared atomicMax + direct append;
// no score tensor, no smem score roundtrip). Exact fp64 rescore unchanged.
// ---------------------------------------------------------------------------

#define MDIM 8192
#define CDIM 8192
#define KDIM 1024
#define QSCALE 25.0f
#define DEQ (2.0f / (QSCALE * QSCALE))   // 2/625
#define MARGIN 10.0f
#define CAP 512                           // per-row candidate capacity

__device__ int8_t  g_x8 [(size_t)MDIM * KDIM];
__device__ int8_t  g_cb8[(size_t)CDIM * KDIM];
__device__ float   g_c2[CDIM];
__device__ int     g_cnt[MDIM];
__device__ float2  g_cand[(size_t)MDIM * CAP];    // (score, col-as-int-bits)

// ---------------- helpers ---------------------------------------------------
__device__ __forceinline__ uint32_t smem_u32(const void* p) {
    uint32_t a;
    asm("{ .reg .u64 t; cvta.to.shared.u64 t, %1; cvt.u32.u64 %0, t; }"
        : "=r"(a) : "l"(p));
    return a;
}
__device__ __forceinline__ void cp16(uint32_t s, const void* g) {
    asm volatile("cp.async.cg.shared.global [%0], [%1], 16;"
                 :: "r"(s), "l"(g) : "memory");
}
__device__ __forceinline__ void ldsm4(uint32_t* r, uint32_t addr) {
    asm volatile("ldmatrix.sync.aligned.m8n8.x4.shared.b16 {%0,%1,%2,%3}, [%4];"
        : "=r"(r[0]), "=r"(r[1]), "=r"(r[2]), "=r"(r[3]) : "r"(addr));
}
__device__ __forceinline__ void mma_s8(int* d, const uint32_t* a,
                                       uint32_t b0, uint32_t b1) {
    asm volatile(
        "mma.sync.aligned.m16n8k32.row.col.s32.s8.s8.s32 "
        "{%0,%1,%2,%3}, {%4,%5,%6,%7}, {%8,%9}, {%0,%1,%2,%3};"
        : "+r"(d[0]), "+r"(d[1]), "+r"(d[2]), "+r"(d[3])
        : "r"(a[0]), "r"(a[1]), "r"(a[2]), "r"(a[3]), "r"(b0), "r"(b1));
}
__device__ __forceinline__ void mbar_init(uint32_t addr, uint32_t cnt) {
    asm volatile("mbarrier.init.shared.b64 [%0], %1;" :: "r"(addr), "r"(cnt) : "memory");
}
__device__ __forceinline__ void mbar_wait(uint32_t addr, uint32_t parity) {
    asm volatile(
        "{\n\t.reg .pred P;\n"
        "WL_%=:\n\t"
        "mbarrier.try_wait.parity.acquire.cta.shared::cta.b64 P, [%0], %1, 0x989680;\n\t"
        "@P bra WD_%=;\n\t"
        "bra WL_%=;\n"
        "WD_%=:\n\t}"
        :: "r"(addr), "r"(parity) : "memory");
}
__device__ __forceinline__ void mbar_arrive(uint32_t addr) {
    asm volatile("mbarrier.arrive.release.cta.shared::cta.b64 _, [%0];"
                 :: "r"(addr) : "memory");
}
__device__ __forceinline__ void cpasync_mbar_arrive_noinc(uint32_t addr) {
    asm volatile("cp.async.mbarrier.arrive.noinc.shared.b64 [%0];"
                 :: "r"(addr) : "memory");
}
// order-preserving float<->uint
__device__ __forceinline__ uint32_t ford(float f) {
    uint32_t u = __float_as_uint(f);
    return (u & 0x80000000u) ? ~u : (u | 0x80000000u);
}
__device__ __forceinline__ float unford(uint32_t u) {
    return (u & 0x80000000u) ? __uint_as_float(u ^ 0x80000000u)
                             : __uint_as_float(~u);
}

// ---------------- kernel 0a: fp32 -> s8 (x) ---------------------------------
__device__ __forceinline__ uint32_t q4(float4 v) {
    int a = __float2int_rn(v.x * QSCALE);
    int b = __float2int_rn(v.y * QSCALE);
    int c = __float2int_rn(v.z * QSCALE);
    int d = __float2int_rn(v.w * QSCALE);
    a = max(-127, min(127, a)); b = max(-127, min(127, b));
    c = max(-127, min(127, c)); d = max(-127, min(127, d));
    return (uint32_t)(uint8_t)a | ((uint32_t)(uint8_t)b << 8) |
           ((uint32_t)(uint8_t)c << 16) | ((uint32_t)(uint8_t)d << 24);
}
__global__ void convert_s8(const float* __restrict__ s,
                           int8_t* __restrict__ d, int n) {
    int i = (blockIdx.x * blockDim.x + threadIdx.x) * 8;
    if (i >= n) return;
    float4 v0 = *reinterpret_cast<const float4*>(s + i);
    float4 v1 = *reinterpret_cast<const float4*>(s + i + 4);
    uint2 o; o.x = q4(v0); o.y = q4(v1);
    *reinterpret_cast<uint2*>(d + i) = o;
}

// ---------------- kernel 0b: cb convert + row norms (fused) ------------------
__global__ __launch_bounds__(256) void convert_cb_c2(
    const float* __restrict__ cb, int8_t* __restrict__ d)
{
    __shared__ float sred[8];
    const int row  = blockIdx.x;
    const int t    = threadIdx.x;
    const int lane = t & 31;
    const int wrp  = t >> 5;
    float4 v = *reinterpret_cast<const float4*>(cb + (size_t)row * KDIM + t * 4);
    *reinterpret_cast<uint32_t*>(d + (size_t)row * KDIM + t * 4) = q4(v);
    float s = v.x * v.x + v.y * v.y + v.z * v.z + v.w * v.w;
    #pragma unroll
    for (int o = 16; o; o >>= 1) s += __shfl_xor_sync(0xffffffffu, s, o);
    if (lane == 0) sred[wrp] = s;
    __syncthreads();
    if (t == 0) {
        float tot = 0.f;
        #pragma unroll
        for (int w = 0; w < 8; w++) tot += sred[w];
        g_c2[row] = tot;
    }
}

// ---------------- kernel 0c: zero per-row counters ---------------------------
__global__ void init_cnt() {
    int i = blockIdx.x * blockDim.x + threadIdx.x;
    if (i < MDIM) g_cnt[i] = 0;
}

// ---------------- kernel 2: int8 screen GEMM + register-path extract --------
// BM=BN=128, BK=128 (128B rows, SW128). 320 thr: warps 0-7 consumers
// (64x32, s32 acc), warps 8 (A) / 9 (B) producers. 3-stage mbar pipeline.
#define NSTAGE 3
#define TILE_BYTES  16384
#define STAGE_BYTES 32768
#define NS (KDIM / 128)            // 8 k-stages
#define SMEM_TOT (1024 + NSTAGE * STAGE_BYTES)

__global__ __launch_bounds__(320, 2) void screen_gemm() {
    extern __shared__ __align__(1024) char smem[];
    const uint32_t base  = smem_u32(smem);
    const uint32_t mb    = base;                 // full[s]=+s*16, empty[s]=+s*16+8
    const uint32_t tiles = base + 1024;
    uint32_t* rmx = reinterpret_cast<uint32_t*>(smem + 1024);  // 128 words, post-mainloop

    const int t    = threadIdx.x;
    const int lane = t & 31;
    const int wid  = t >> 5;
    const int bm   = blockIdx.y * 128;
    const int bn   = blockIdx.x * 128;

    if (t == 0) {
        #pragma unroll
        for (int s = 0; s < NSTAGE; s++) {
            mbar_init(mb + s * 16,     64);
            mbar_init(mb + s * 16 + 8, 8);
        }
    }
    __syncthreads();

    if (wid >= 8) {
        // ================= PRODUCER (warp 8: A, warp 9: B) ==================
        const int pw   = wid - 8;
        const int ch   = lane & 7;
        const int row0 = lane >> 3;
        const int8_t* gsrc = (pw == 0)
            ? g_x8  + (size_t)(bm + row0) * KDIM + ch * 16
            : g_cb8 + (size_t)(bn + row0) * KDIM + ch * 16;
        const uint32_t tile_off = (uint32_t)pw * TILE_BYTES;
        const uint32_t rbase = (uint32_t)row0 * 128;
        const uint32_t sw0 = (uint32_t)((ch ^ row0) << 4);
        const uint32_t sw1 = (uint32_t)((ch ^ row0 ^ 4) << 4);

        int b = 0, ep = 0;
        for (int s = 0; s < NS; s++) {
            if (s >= NSTAGE) mbar_wait(mb + b * 16 + 8, ep);
            const uint32_t so = tiles + b * STAGE_BYTES + tile_off + rbase;
            const int8_t* g = gsrc + s * 128;
            #pragma unroll
            for (int i = 0; i < 32; i++)
                cp16(so + (uint32_t)i * 512 + ((i & 1) ? sw1 : sw0),
                     g + (size_t)i * 4 * KDIM);
            cpasync_mbar_arrive_noinc(mb + b * 16);
            if (++b == NSTAGE) { b = 0; if (s >= NSTAGE) ep ^= 1; }
        }
        return;
    }

    // ===================== CONSUMER (warps 0-7, 64x32 tiles) ================
    const int wm = wid >> 2;
    const int wn = wid & 3;
    const int rbase = lane & 15;
    const uint32_t lh = (uint32_t)(lane >> 4);

    uint32_t off[6];
    #pragma unroll
    for (int mi = 0; mi < 4; mi++) {
        int row = wm * 64 + mi * 16 + rbase;
        off[mi] = (uint32_t)row * 128 + ((lh ^ (uint32_t)(row & 7)) << 4);
    }
    #pragma unroll
    for (int g = 0; g < 2; g++) {
        int row = wn * 32 + g * 16 + rbase;
        off[4 + g] = TILE_BYTES + (uint32_t)row * 128 +
                     ((lh ^ (uint32_t)(row & 7)) << 4);
    }

    int acc[4][4][4];
    #pragma unroll
    for (int i = 0; i < 4; i++)
        #pragma unroll
        for (int j = 0; j < 4; j++)
            #pragma unroll
            for (int k = 0; k < 4; k++) acc[i][j][k] = 0;

    uint32_t fa[4][4], fb[2][4];

    #define LOADK(As, x)                                                      \
        {                                                                     \
            ldsm4(fa[0], (As) + (off[0] ^ (x))); ldsm4(fa[1], (As) + (off[1] ^ (x))); \
            ldsm4(fa[2], (As) + (off[2] ^ (x))); ldsm4(fa[3], (As) + (off[3] ^ (x))); \
            ldsm4(fb[0], (As) + (off[4] ^ (x))); ldsm4(fb[1], (As) + (off[5] ^ (x))); \
        }
    #define MMAK()                                                            \
        {                                                                     \
            _Pragma("unroll")                                                 \
            for (int mi = 0; mi < 4; mi++)                                    \
                _Pragma("unroll")                                             \
                for (int ni = 0; ni < 4; ni++)                                \
                    mma_s8(acc[mi][ni], fa[mi],                               \
                           fb[ni >> 1][ni & 1], fb[ni >> 1][(ni & 1) + 2]);   \
        }

    int b = 0, pf = 0;
    for (int s = 0; s < NS; s++) {
        mbar_wait(mb + b * 16, pf);
        const uint32_t As = tiles + b * STAGE_BYTES;

        LOADK(As, 0x00u)  MMAK()
        LOADK(As, 0x20u)  MMAK()
        LOADK(As, 0x40u)  MMAK()
        LOADK(As, 0x60u)
        if (lane == 0) mbar_arrive(mb + b * 16 + 8);
        MMAK()

        if (++b == NSTAGE) { b = 0; pf ^= 1; }
    }

    // ---- epilogue (register path, consumers only) ----
    // scores: val[mi][ni][k]; rows wm*64+mi*16+(lane>>2)(+8); cols wn*32+ni*8+2*(lane&3)(+1)
    float c2v[8];
    #pragma unroll
    for (int ni = 0; ni < 4; ni++) {
        int n0 = bn + wn * 32 + ni * 8 + 2 * (lane & 3);
        c2v[2 * ni]     = g_c2[n0];
        c2v[2 * ni + 1] = g_c2[n0 + 1];
    }

    if (t < 128) rmx[t] = 0u;                      // decode -> NaN, always overwritten
    asm volatile("bar.sync 1, 256;" ::: "memory");

    // per-thread row maxima, then reduce across the 4 lanes sharing each row
    float rlo[4], rhi[4];
    #pragma unroll
    for (int mi = 0; mi < 4; mi++) {
        float a = -3.4e38f, c = -3.4e38f;
        #pragma unroll
        for (int ni = 0; ni < 4; ni++) {
            a = fmaxf(a, fmaxf(DEQ * (float)acc[mi][ni][0] - c2v[2 * ni],
                               DEQ * (float)acc[mi][ni][1] - c2v[2 * ni + 1]));
            c = fmaxf(c, fmaxf(DEQ * (float)acc[mi][ni][2] - c2v[2 * ni],
                               DEQ * (float)acc[mi][ni][3] - c2v[2 * ni + 1]));
        }
        a = fmaxf(a, __shfl_xor_sync(0xffffffffu, a, 1));
        a = fmaxf(a, __shfl_xor_sync(0xffffffffu, a, 2));
        c = fmaxf(c, __shfl_xor_sync(0xffffffffu, c, 1));
        c = fmaxf(c, __shfl_xor_sync(0xffffffffu, c, 2));
        rlo[mi] = a; rhi[mi] = c;
    }
    if ((lane & 3) == 0) {
        #pragma unroll
        for (int mi = 0; mi < 4; mi++) {
            int r = wm * 64 + mi * 16 + (lane >> 2);
            atomicMax(&rmx[r],     ford(rlo[mi]));
            atomicMax(&rmx[r + 8], ford(rhi[mi]));
        }
    }
    asm volatile("bar.sync 1, 256;" ::: "memory");

    // append candidates within MARGIN of CTA-local row max
    #pragma unroll
    for (int mi = 0; mi < 4; mi++) {
        int rl = wm * 64 + mi * 16 + (lane >> 2);
        float thl = unford(rmx[rl])     - MARGIN;
        float thh = unford(rmx[rl + 8]) - MARGIN;
        int gml = bm + rl, gmh = gml + 8;
        #pragma unroll
        for (int ni = 0; ni < 4; ni++) {
            int n0 = bn + wn * 32 + ni * 8 + 2 * (lane & 3);
            float s0 = DEQ * (float)acc[mi][ni][0] - c2v[2 * ni];
            float s1 = DEQ * (float)acc[mi][ni][1] - c2v[2 * ni + 1];
            float s2 = DEQ * (float)acc[mi][ni][2] - c2v[2 * ni];
            float s3 = DEQ * (float)acc[mi][ni][3] - c2v[2 * ni + 1];
            if (s0 >= thl) { int i = atomicAdd(&g_cnt[gml], 1);
                if (i < CAP) g_cand[(size_t)gml * CAP + i] = make_float2(s0, __int_as_float(n0)); }
            if (s1 >= thl) { int i = atomicAdd(&g_cnt[gml], 1);
                if (i < CAP) g_cand[(size_t)gml * CAP + i] = make_float2(s1, __int_as_float(n0 + 1)); }
            if (s2 >= thh) { int i = atomicAdd(&g_cnt[gmh], 1);
                if (i < CAP) g_cand[(size_t)gmh * CAP + i] = make_float2(s2, __int_as_float(n0)); }
            if (s3 >= thh) { int i = atomicAdd(&g_cnt[gmh], 1);
                if (i < CAP) g_cand[(size_t)gmh * CAP + i] = make_float2(s3, __int_as_float(n0 + 1)); }
        }
    }
}

// ---------------- kernel 3: select + exact fp64 rescore ----------------------
#define MAXSURV 64

__global__ __launch_bounds__(256) void select_rescore(
    const float* __restrict__ x, const float* __restrict__ cb,
    float* __restrict__ out)
{
    __shared__ float  xs[KDIM];
    __shared__ float  smax[8];
    __shared__ double sred[2][8];
    __shared__ float2 sc[CAP];
    __shared__ int    surv[MAXSURV];
    __shared__ int    nsurv;

    const int m    = blockIdx.x;
    const int t    = threadIdx.x;
    const int lane = t & 31;
    const int wrp  = t >> 5;

    {
        const float4* src = reinterpret_cast<const float4*>(x + (size_t)m * KDIM);
        reinterpret_cast<float4*>(xs)[t] = src[t];
    }
    if (t == 0) nsurv = 0;

    const int nc = min(g_cnt[m], CAP);

    float lmax = -3.4e38f;
    for (int j = t; j < nc; j += 256) {
        float2 p = g_cand[(size_t)m * CAP + j];
        sc[j] = p;
        lmax = fmaxf(lmax, p.x);
    }
    #pragma unroll
    for (int o = 16; o; o >>= 1)
        lmax = fmaxf(lmax, __shfl_xor_sync(0xffffffffu, lmax, o));
    if (lane == 0) smax[wrp] = lmax;
    __syncthreads();
    float rowmax = smax[0];
    #pragma unroll
    for (int w = 1; w < 8; w++) rowmax = fmaxf(rowmax, smax[w]);
    const float th = rowmax - MARGIN;

    for (int j = t; j < nc; j += 256) {
        if (sc[j].x >= th) {
            int p = atomicAdd(&nsurv, 1);
            if (p < MAXSURV) surv[p] = __float_as_int(sc[j].y);
        }
    }
    __syncthreads();
    const int ns = min(nsurv, MAXSURV);

    double bestS = -1e300;
    int    bestI = 0x7FFFFFFF;
    for (int ci = 0; ci < ns; ci++) {
        int c = surv[ci];
        const float* crow = cb + (size_t)c * KDIM;
        double s = 0.0, cc = 0.0;
        for (int d = t; d < KDIM; d += 256) {
            double cv = (double)crow[d];
            s  += (double)xs[d] * cv;
            cc += cv * cv;
        }
        #pragma unroll
        for (int o = 16; o; o >>= 1) {
            s  += __shfl_xor_sync(0xffffffffu, s,  o);
            cc += __shfl_xor_sync(0xffffffffu, cc, o);
        }
        if (lane == 0) { sred[0][wrp] = s; sred[1][wrp] = cc; }
        __syncthreads();
        double st = 0.0, ct = 0.0;
        #pragma unroll
        for (int w = 0; w < 8; w++) { st += sred[0][w]; ct += sred[1][w]; }
        __syncthreads();
        double scv = 2.0 * st - ct;
        if (scv > bestS || (scv == bestS && c < bestI)) { bestS = scv; bestI = c; }
    }

    const float4* src = reinterpret_cast<const float4*>(cb + (size_t)bestI * KDIM);
    float4* dst = reinterpret_cast<float4*>(out + (size_t)m * KDIM);
    dst[t] = src[t];
}

// ---------------- launch ------------------------------------------------------
extern "C" void kernel_launch(void* const* d_in, const int* in_sizes, int n_in,
                              void* d_out, int out_size)
{
    const float* x  = (const float*)d_in[0];   // [8192, 1024]
    const float* cb = (const float*)d_in[1];   // [8192, 1024]
    float* out = (float*)d_out;

    const int NX = MDIM * KDIM;

    int8_t *x8_p = nullptr, *cb8_p = nullptr;
    cudaGetSymbolAddress((void**)&x8_p, g_x8);
    cudaGetSymbolAddress((void**)&cb8_p, g_cb8);

    cudaFuncSetAttribute(screen_gemm,
                         cudaFuncAttributeMaxDynamicSharedMemorySize, SMEM_TOT);

    init_cnt<<<MDIM / 256, 256>>>();
    convert_s8<<<NX / 2048, 256>>>(x, x8_p, NX);
    convert_cb_c2<<<CDIM, 256>>>(cb, cb8_p);

    dim3 grid(CDIM / 128, MDIM / 128);
    screen_gemm<<<grid, 320, SMEM_TOT>>>();

    select_rescore<<<MDIM, 256>>>(x, cb, out);
}